// round 10
// baseline (speedup 1.0000x reference)
#include <cuda_runtime.h>
#include <cuda_bf16.h>
#include <cstdint>

// Problem constants
#define BB   8
#define NN   4096
#define MM   1024
#define CIN  32
#define KNB  64
#define NEGV (-1e10f)
#define R2F  (0.04f)

// Scratch (device globals: allocation-free)
__device__ int   g_fps[BB * MM];
__device__ float g_t[(size_t)BB * NN * 64];
__device__ int   g_nbr[(size_t)BB * MM * KNB];

typedef unsigned long long ull;

// ---------------- helpers: packed f32x2 ----------------
__device__ __forceinline__ ull pack2(float lo, float hi) {
    ull r; asm("mov.b64 %0, {%1, %2};" : "=l"(r) : "f"(lo), "f"(hi)); return r;
}
__device__ __forceinline__ ull bc2(float v) {
    ull r; asm("mov.b64 %0, {%1, %1};" : "=l"(r) : "f"(v)); return r;
}
__device__ __forceinline__ void unpack2(ull v, float& lo, float& hi) {
    asm("mov.b64 {%0, %1}, %2;" : "=f"(lo), "=f"(hi) : "l"(v));
}
__device__ __forceinline__ void fma2(ull& acc, ull a, ull b) {
    asm("fma.rn.f32x2 %0, %1, %2, %0;" : "+l"(acc) : "l"(a), "l"(b));
}
__device__ __forceinline__ ull add2(ull a, ull b) {
    ull r; asm("add.rn.f32x2 %0, %1, %2;" : "=l"(r) : "l"(a), "l"(b)); return r;
}
__device__ __forceinline__ ull mul2(ull a, ull b) {
    ull r; asm("mul.rn.f32x2 %0, %1, %2;" : "=l"(r) : "l"(a), "l"(b)); return r;
}
__device__ __forceinline__ ull sqdist2(ull X, ull Y, ull Z, ull ncx, ull ncy, ull ncz) {
    ull dx = add2(X, ncx), dy = add2(Y, ncy), dz = add2(Z, ncz);
    return add2(add2(mul2(dx, dx), mul2(dy, dy)), mul2(dz, dz));
}
__device__ __forceinline__ ull umax64(ull a, ull b) { return a > b ? a : b; }

__device__ __forceinline__ float sqdist(float ax, float ay, float az,
                                        float bx, float by, float bz) {
    float dx = ax - bx, dy = ay - by, dz = az - bz;
    return __fadd_rn(__fadd_rn(__fmul_rn(dx, dx), __fmul_rn(dy, dy)), __fmul_rn(dz, dz));
}

// ---------------- Kernel A: farthest point sampling (v3, unchanged) ----------------
__global__ void __launch_bounds__(256) fps_kernel(const float* __restrict__ pos) {
    extern __shared__ float sm[];
    float* sx = sm;
    float* sy = sm + NN;
    float* sz = sm + 2 * NN;
    __shared__ alignas(16) ull skey[2][8];

    const int b = blockIdx.x;
    const int tid = threadIdx.x;
    const float* pb = pos + (size_t)b * NN * 3;

    for (int i = tid; i < NN; i += 256) {
        sx[i] = pb[i * 3 + 0];
        sy[i] = pb[i * 3 + 1];
        sz[i] = pb[i * 3 + 2];
    }
    if (tid == 0) g_fps[b * MM] = 0;
    __syncthreads();

    const int base = tid * 16;
    ull X[8], Y[8], Z[8];
#pragma unroll
    for (int j = 0; j < 8; ++j) {
        X[j] = pack2(sx[base + 2 * j], sx[base + 2 * j + 1]);
        Y[j] = pack2(sy[base + 2 * j], sy[base + 2 * j + 1]);
        Z[j] = pack2(sz[base + 2 * j], sz[base + 2 * j + 1]);
    }
    float dmin[16];
#pragma unroll
    for (int j = 0; j < 16; ++j) dmin[j] = 1e10f;

    int last = 0;
    for (int it = 1; it < MM; ++it) {
        const float lx = sx[last], ly = sy[last], lz = sz[last];
        const ull nlx = bc2(-lx), nly = bc2(-ly), nlz = bc2(-lz);
        float bv = -1.0f; int bi = 0;
#pragma unroll
        for (int j = 0; j < 8; ++j) {
            ull s = sqdist2(X[j], Y[j], Z[j], nlx, nly, nlz);
            float d0, d1; unpack2(s, d0, d1);
            float m0 = fminf(dmin[2 * j + 0], d0); dmin[2 * j + 0] = m0;
            float m1 = fminf(dmin[2 * j + 1], d1); dmin[2 * j + 1] = m1;
            if (m0 > bv) { bv = m0; bi = base + 2 * j; }
            if (m1 > bv) { bv = m1; bi = base + 2 * j + 1; }
        }
        ull key = (((ull)__float_as_uint(bv)) << 32) | (unsigned)(4095 - bi);
#pragma unroll
        for (int off = 16; off; off >>= 1) {
            ull o = __shfl_down_sync(0xffffffffu, key, off);
            key = umax64(key, o);
        }
        const int p = it & 1;
        if ((tid & 31) == 0) skey[p][tid >> 5] = key;
        __syncthreads();
        const ulonglong2* sk = reinterpret_cast<const ulonglong2*>(skey[p]);
        ulonglong2 a = sk[0], c = sk[1], d = sk[2], e = sk[3];
        ull m = umax64(umax64(umax64(a.x, a.y), umax64(c.x, c.y)),
                       umax64(umax64(d.x, d.y), umax64(e.x, e.y)));
        last = 4095 - (int)(m & 0xFFFFull);
        if (tid == 0) g_fps[b * MM + it] = last;
    }
}

// ---------------- Kernel B: ball query + exact 64-NN selection (unchanged) ----------------
#define BCAP 512
__global__ void ballq_kernel(const float* __restrict__ pos) {
    extern __shared__ float sm[];
    float2* spx = (float2*)sm;
    float2* spy = spx + 2048;
    float2* spz = spy + 2048;
    ull* bufAll = (ull*)(spz + 2048);

    const int b = blockIdx.y;
    const int chunk = blockIdx.x;
    const int tid = threadIdx.x;
    const int warpId = tid >> 5;
    const int lane = tid & 31;
    const unsigned lanelt = (1u << lane) - 1u;
    const float* pb = pos + (size_t)b * NN * 3;

    for (int k = tid; k < NN * 3; k += 256) {
        float f = pb[k];
        int i = k / 3, comp = k - 3 * i;
        float* dst = (comp == 0) ? (float*)spx : (comp == 1) ? (float*)spy : (float*)spz;
        dst[(i & 2047) * 2 + (i >> 11)] = f;
    }
    __syncthreads();

    const ull* px = (const ull*)spx;
    const ull* py = (const ull*)spy;
    const ull* pz = (const ull*)spz;
    ull* buf = bufAll + (size_t)warpId * BCAP;

    for (int cc = 0; cc < 2; ++cc) {
        const int c = chunk * 16 + warpId * 2 + cc;
        const int gi = g_fps[b * MM + c];
        const int hi = gi >> 11, ii = gi & 2047;
        float2 t;
        t = spx[ii]; const float cx = hi ? t.y : t.x;
        t = spy[ii]; const float cy = hi ? t.y : t.x;
        t = spz[ii]; const float cz = hi ? t.y : t.x;
        const ull ncx = bc2(-cx), ncy = bc2(-cy), ncz = bc2(-cz);

        int cnt = 0;
        for (int basej = 0; basej < 2048; basej += 32) {
            const int j = basej + lane;
            ull s = sqdist2(px[j], py[j], pz[j], ncx, ncy, ncz);
            float d0, d1; unpack2(s, d0, d1);
            bool in0 = (d0 <= R2F);
            unsigned m0 = __ballot_sync(0xffffffffu, in0);
            if (in0) {
                int off = cnt + __popc(m0 & lanelt);
                if (off < BCAP)
                    buf[off] = (((ull)__float_as_uint(d0)) << 32) | (unsigned)j;
            }
            cnt += __popc(m0);
            bool in1 = (d1 <= R2F);
            unsigned m1 = __ballot_sync(0xffffffffu, in1);
            if (in1) {
                int off = cnt + __popc(m1 & lanelt);
                if (off < BCAP)
                    buf[off] = (((ull)__float_as_uint(d1)) << 32) | (unsigned)(j + 2048);
            }
            cnt += __popc(m1);
        }
        int ccnt = min(cnt, BCAP);
        __syncwarp();
        if (ccnt > KNB) {
            int n = KNB;
            while (n < ccnt) n <<= 1;
            for (int i = ccnt + lane; i < n; i += 32) buf[i] = 0xffffffffffffffffull;
            __syncwarp();
            for (int k2 = 2; k2 <= n; k2 <<= 1) {
                for (int j2 = k2 >> 1; j2 > 0; j2 >>= 1) {
                    for (int i = lane; i < n; i += 32) {
                        int ixj = i ^ j2;
                        if (ixj > i) {
                            ull a = buf[i], q = buf[ixj];
                            bool up = ((i & k2) == 0);
                            if ((a > q) == up) { buf[i] = q; buf[ixj] = a; }
                        }
                    }
                    __syncwarp();
                }
            }
        }
        int nv = min(ccnt, KNB);
        for (int s2 = lane; s2 < KNB; s2 += 32) {
            int outi = (s2 < nv) ? (int)(buf[s2] & 0xffffffffull) : -1;
            g_nbr[((size_t)(b * MM + c)) * KNB + s2] = outi;
        }
        __syncwarp();
    }
}

// ---------------- Kernel C: t = x @ W1[0:32,:] (unchanged) ----------------
__global__ void feat_kernel(const float* __restrict__ x, const float* __restrict__ W1) {
    __shared__ float Ws[CIN * 64];
    const int tid = threadIdx.x;
    for (int i = tid; i < CIN * 64; i += 256) Ws[i] = W1[i];
    __syncthreads();

    int g = blockIdx.x * 256 + tid;
    int p = g >> 2;
    int q = g & 3;

    float xr[32];
    const float4* xp = reinterpret_cast<const float4*>(x + (size_t)p * CIN);
#pragma unroll
    for (int k = 0; k < 8; ++k) {
        float4 v = xp[k];
        xr[4 * k + 0] = v.x; xr[4 * k + 1] = v.y; xr[4 * k + 2] = v.z; xr[4 * k + 3] = v.w;
    }
    float acc[16];
#pragma unroll
    for (int o = 0; o < 16; ++o) acc[o] = 0.0f;
#pragma unroll
    for (int i = 0; i < 32; ++i) {
        float xv = xr[i];
        const float4* wrow = reinterpret_cast<const float4*>(Ws + i * 64 + q * 16);
#pragma unroll
        for (int o4 = 0; o4 < 4; ++o4) {
            float4 w = wrow[o4];
            acc[o4 * 4 + 0] += xv * w.x;
            acc[o4 * 4 + 1] += xv * w.y;
            acc[o4 * 4 + 2] += xv * w.z;
            acc[o4 * 4 + 3] += xv * w.w;
        }
    }
    float4* tp = reinterpret_cast<float4*>(g_t + (size_t)p * 64 + q * 16);
#pragma unroll
    for (int o4 = 0; o4 < 4; ++o4)
        tp[o4] = make_float4(acc[o4 * 4 + 0], acc[o4 * 4 + 1], acc[o4 * 4 + 2], acc[o4 * 4 + 3]);
}

// ---------------- Kernel D v3: register-tiled SGEMM MLP + max-aggregate ----------------
// Block = 128 threads = 2 centroids x 64 threads.
// Phase 1: thread = neighbor, compute h[64], store transposed H[k][m] to smem.
// Phase 2/3: 8x8 register-tile GEMMs (neighbor pairs packed f32x2 over M).
// smem floats:
#define C_W2  0        /* 4096 */
#define C_W3  4096     /* 8192 */
#define C_W1P 12288    /* 192  */
#define C_B1  12480    /* 64   */
#define C_B2  12544    /* 64   */
#define C_B3  12608    /* 128  */
#define C_VM  12736    /* 4 u32, pad 16 */
#define C_HB  12752    /* 2 x 64 rows x 34 ull (=68 floats) = 8704 floats */
#define C_TOT 21456

__global__ void __launch_bounds__(128, 2) conv_kernel(
    const float* __restrict__ pos,
    const float* __restrict__ W1, const float* __restrict__ b1,
    const float* __restrict__ W2, const float* __restrict__ b2,
    const float* __restrict__ W3, const float* __restrict__ b3,
    float* __restrict__ out, int out_size)
{
    extern __shared__ float smf[];
    const int tid = threadIdx.x;

    for (int i = tid; i < 4096; i += 128) smf[C_W2 + i] = W2[i];
    for (int i = tid; i < 8192; i += 128) smf[C_W3 + i] = W3[i];
    for (int i = tid; i < 192; i += 128)  smf[C_W1P + i] = W1[CIN * 64 + i];
    if (tid < 64)  smf[C_B1 + tid] = b1[tid];
    if (tid < 64)  smf[C_B2 + tid] = b2[tid];
    if (tid < 128) smf[C_B3 + tid] = b3[tid];

    const int c    = tid >> 6;       // centroid slot in block
    const int gtid = tid & 63;       // 0..63 within centroid group
    const int cid  = blockIdx.x * 2 + c;
    const int b    = cid >> 10;
    float* Hf = smf + C_HB + c * 4352;          // [64 rows][68 floats]
    ull*   Hb = (ull*)(smf + C_HB) + c * 2176;  // same memory, [64][34] ull

    // ---- Phase 1: per-neighbor layer 1 ----
    const int gi = g_fps[cid];
    const float* pb = pos + (size_t)b * NN * 3;
    const float cx = pb[gi * 3 + 0], cy = pb[gi * 3 + 1], cz = pb[gi * 3 + 2];

    const int nj = g_nbr[(size_t)cid * KNB + gtid];
    const bool valid = (nj >= 0);
    const int jj = valid ? nj : gi;
    const float rx = pb[jj * 3 + 0] - cx;
    const float ry = pb[jj * 3 + 1] - cy;
    const float rz = pb[jj * 3 + 2] - cz;

    unsigned vm = __ballot_sync(0xffffffffu, valid);
    if ((tid & 31) == 0)
        reinterpret_cast<unsigned*>(smf + C_VM)[c * 2 + (gtid >> 5)] = vm;

    __syncthreads();   // weights+biases loaded (also covers VM store ordering w/ later sync)

    {
        float h[64];
        const float4* tp = reinterpret_cast<const float4*>(g_t + ((size_t)b * NN + jj) * 64);
#pragma unroll
        for (int o4 = 0; o4 < 16; ++o4) {
            float4 tv = tp[o4];
            float4 bb = reinterpret_cast<const float4*>(smf + C_B1)[o4];
            float4 w0 = reinterpret_cast<const float4*>(smf + C_W1P)[o4];
            float4 w1 = reinterpret_cast<const float4*>(smf + C_W1P + 64)[o4];
            float4 w2r = reinterpret_cast<const float4*>(smf + C_W1P + 128)[o4];
            h[4 * o4 + 0] = fmaxf(tv.x + bb.x + rx * w0.x + ry * w1.x + rz * w2r.x, 0.0f);
            h[4 * o4 + 1] = fmaxf(tv.y + bb.y + rx * w0.y + ry * w1.y + rz * w2r.y, 0.0f);
            h[4 * o4 + 2] = fmaxf(tv.z + bb.z + rx * w0.z + ry * w1.z + rz * w2r.z, 0.0f);
            h[4 * o4 + 3] = fmaxf(tv.w + bb.w + rx * w0.w + ry * w1.w + rz * w2r.w, 0.0f);
        }
        // transpose-store: H[k][m] — warp writes one row per step, conflict-free
#pragma unroll
        for (int k = 0; k < 64; ++k)
            Hf[k * 68 + gtid] = h[k];
    }
    __syncthreads();

    // ---- GEMM phase: thread tile 8 neighbors (4 f32x2 pairs) x 8 outputs ----
    const int mt = gtid & 7;
    const int nt = gtid >> 3;
    const unsigned vm0 = reinterpret_cast<unsigned*>(smf + C_VM)[c * 2 + 0];
    const unsigned vm1 = reinterpret_cast<unsigned*>(smf + C_VM)[c * 2 + 1];
    bool vld[8];
#pragma unroll
    for (int mm = 0; mm < 8; ++mm) {
        int m = mt * 8 + mm;
        vld[mm] = ((m < 32 ? (vm0 >> m) : (vm1 >> (m - 32))) & 1u) != 0;
    }

    // ---- Layer 2: C[64m,64n] = relu(H @ W2 + b2) ----
    ull acc[32];
#pragma unroll
    for (int n = 0; n < 8; ++n) {
        ull bv = bc2(smf[C_B2 + nt * 8 + n]);
#pragma unroll
        for (int j = 0; j < 4; ++j) acc[n * 4 + j] = bv;
    }
#pragma unroll 4
    for (int k = 0; k < 64; ++k) {
        const ulonglong2* hpp = reinterpret_cast<const ulonglong2*>(Hb + k * 34 + mt * 4);
        ulonglong2 ha = hpp[0], hc = hpp[1];
        const float4* wp = reinterpret_cast<const float4*>(smf + C_W2 + k * 64 + nt * 8);
        float4 wa = wp[0], wb = wp[1];
        float wv[8] = {wa.x, wa.y, wa.z, wa.w, wb.x, wb.y, wb.z, wb.w};
#pragma unroll
        for (int n = 0; n < 8; ++n) {
            ull w = bc2(wv[n]);
            fma2(acc[n * 4 + 0], ha.x, w);
            fma2(acc[n * 4 + 1], ha.y, w);
            fma2(acc[n * 4 + 2], hc.x, w);
            fma2(acc[n * 4 + 3], hc.y, w);
        }
    }
    __syncthreads();   // all H reads done before overwrite
    // relu + store H2 into same buffer: H2[n][m]
#pragma unroll
    for (int n = 0; n < 8; ++n) {
        int row = nt * 8 + n;
#pragma unroll
        for (int j = 0; j < 4; ++j) {
            float lo, hi;
            unpack2(acc[n * 4 + j], lo, hi);
            acc[n * 4 + j] = pack2(fmaxf(lo, 0.0f), fmaxf(hi, 0.0f));
        }
        ulonglong2* dst = reinterpret_cast<ulonglong2*>(Hb + row * 34 + mt * 4);
        ulonglong2 t0; t0.x = acc[n * 4 + 0]; t0.y = acc[n * 4 + 1];
        ulonglong2 t1; t1.x = acc[n * 4 + 2]; t1.y = acc[n * 4 + 3];
        dst[0] = t0; dst[1] = t1;
    }
    __syncthreads();   // H2 fully written

    // ---- Layer 3: two 64-output halves + masked max ----
#pragma unroll 1
    for (int nh = 0; nh < 2; ++nh) {
        ull a3[32];
#pragma unroll
        for (int n = 0; n < 8; ++n) {
            ull bv = bc2(smf[C_B3 + nh * 64 + nt * 8 + n]);
#pragma unroll
            for (int j = 0; j < 4; ++j) a3[n * 4 + j] = bv;
        }
#pragma unroll 4
        for (int k = 0; k < 64; ++k) {
            const ulonglong2* hpp = reinterpret_cast<const ulonglong2*>(Hb + k * 34 + mt * 4);
            ulonglong2 ha = hpp[0], hc = hpp[1];
            const float4* wp = reinterpret_cast<const float4*>(smf + C_W3 + k * 128 + nh * 64 + nt * 8);
            float4 wa = wp[0], wb = wp[1];
            float wv[8] = {wa.x, wa.y, wa.z, wa.w, wb.x, wb.y, wb.z, wb.w};
#pragma unroll
            for (int n = 0; n < 8; ++n) {
                ull w = bc2(wv[n]);
                fma2(a3[n * 4 + 0], ha.x, w);
                fma2(a3[n * 4 + 1], ha.y, w);
                fma2(a3[n * 4 + 2], hc.x, w);
                fma2(a3[n * 4 + 3], hc.y, w);
            }
        }
        // mask + in-thread max over 8 neighbors
        float vmx[8];
#pragma unroll
        for (int n = 0; n < 8; ++n) {
            float vn = NEGV;
#pragma unroll
            for (int j = 0; j < 4; ++j) {
                float lo, hi;
                unpack2(a3[n * 4 + j], lo, hi);
                vn = fmaxf(vn, vld[2 * j + 0] ? lo : NEGV);
                vn = fmaxf(vn, vld[2 * j + 1] ? hi : NEGV);
            }
            vmx[n] = vn;
        }
        // cross-lane max over mt (lanes differing in low 3 bits)
#pragma unroll
        for (int off = 1; off <= 4; off <<= 1) {
#pragma unroll
            for (int n = 0; n < 8; ++n)
                vmx[n] = fmaxf(vmx[n], __shfl_xor_sync(0xffffffffu, vmx[n], off));
        }
        if (mt == 0) {
            int off0 = cid * 128 + nh * 64 + nt * 8;
#pragma unroll
            for (int n = 0; n < 8; ++n)
                if (off0 + n < out_size) out[off0 + n] = vmx[n];
        }
    }
}

// ---------------- Kernel E: pos_out + batch_out tails ----------------
__global__ void tail_kernel(const float* __restrict__ pos, float* __restrict__ out, int out_size) {
    int i = blockIdx.x * 256 + threadIdx.x;
    if (i >= BB * MM) return;
    int b = i >> 10;
    int gi = g_fps[i];
    const float* pb = pos + (size_t)b * NN * 3;
    const int OX = BB * MM * 128;
    const int OP = OX + BB * MM * 3;
    const int OT = OP + BB * MM;
    if (out_size >= OP) {
        out[OX + i * 3 + 0] = pb[gi * 3 + 0];
        out[OX + i * 3 + 1] = pb[gi * 3 + 1];
        out[OX + i * 3 + 2] = pb[gi * 3 + 2];
    }
    if (out_size >= OT) out[OP + i] = (float)b;
}

extern "C" void kernel_launch(void* const* d_in, const int* in_sizes, int n_in,
                              void* d_out, int out_size) {
    const float* x   = (const float*)d_in[0];
    const float* pos = (const float*)d_in[1];
    const float* W1  = (const float*)d_in[3];
    const float* b1  = (const float*)d_in[4];
    const float* W2  = (const float*)d_in[5];
    const float* b2  = (const float*)d_in[6];
    const float* W3  = (const float*)d_in[7];
    const float* b3  = (const float*)d_in[8];
    float* out = (float*)d_out;

    const int smA = 3 * NN * 4;                        // 49152
    const int smB = 3 * NN * 4 + 8 * BCAP * 8;         // 81920
    const int smD = C_TOT * 4;                         // 85824

    cudaFuncSetAttribute(fps_kernel,   cudaFuncAttributeMaxDynamicSharedMemorySize, smA);
    cudaFuncSetAttribute(ballq_kernel, cudaFuncAttributeMaxDynamicSharedMemorySize, smB);
    cudaFuncSetAttribute(conv_kernel,  cudaFuncAttributeMaxDynamicSharedMemorySize, smD);
    cudaFuncSetAttribute(fps_kernel,   cudaFuncAttributePreferredSharedMemoryCarveout, 100);
    cudaFuncSetAttribute(ballq_kernel, cudaFuncAttributePreferredSharedMemoryCarveout, 100);
    cudaFuncSetAttribute(conv_kernel,  cudaFuncAttributePreferredSharedMemoryCarveout, 100);

    fps_kernel<<<BB, 256, smA>>>(pos);
    ballq_kernel<<<dim3(64, BB), 256, smB>>>(pos);
    feat_kernel<<<(BB * NN * 4) / 256, 256>>>(x, W1);
    conv_kernel<<<(BB * MM) / 2, 128, smD>>>(pos, W1, b1, W2, b2, W3, b3, out, out_size);
    tail_kernel<<<(BB * MM) / 256, 256>>>(pos, out, out_size);
}

// round 13
// speedup vs baseline: 1.5068x; 1.5068x over previous
#include <cuda_runtime.h>
#include <cuda_bf16.h>
#include <cstdint>

// Problem constants
#define BB   8
#define NN   4096
#define MM   1024
#define CIN  32
#define KNB  64
#define NEGV (-1e10f)
#define R2F  (0.04f)

// Scratch (device globals: allocation-free)
__device__ int   g_fps[BB * MM];
__device__ float g_t[(size_t)BB * NN * 64];
__device__ int   g_nbr[(size_t)BB * MM * KNB];

typedef unsigned long long ull;

// ---------------- helpers: packed f32x2 ----------------
__device__ __forceinline__ ull pack2(float lo, float hi) {
    ull r; asm("mov.b64 %0, {%1, %2};" : "=l"(r) : "f"(lo), "f"(hi)); return r;
}
__device__ __forceinline__ ull bc2(float v) {
    ull r; asm("mov.b64 %0, {%1, %1};" : "=l"(r) : "f"(v)); return r;
}
__device__ __forceinline__ void unpack2(ull v, float& lo, float& hi) {
    asm("mov.b64 {%0, %1}, %2;" : "=f"(lo), "=f"(hi) : "l"(v));
}
__device__ __forceinline__ void fma2(ull& acc, ull a, ull b) {
    asm("fma.rn.f32x2 %0, %1, %2, %0;" : "+l"(acc) : "l"(a), "l"(b));
}
__device__ __forceinline__ ull add2(ull a, ull b) {
    ull r; asm("add.rn.f32x2 %0, %1, %2;" : "=l"(r) : "l"(a), "l"(b)); return r;
}
__device__ __forceinline__ ull mul2(ull a, ull b) {
    ull r; asm("mul.rn.f32x2 %0, %1, %2;" : "=l"(r) : "l"(a), "l"(b)); return r;
}
// per-component identical to __fadd_rn(__fadd_rn(__fmul_rn,__fmul_rn),__fmul_rn)
__device__ __forceinline__ ull sqdist2(ull X, ull Y, ull Z, ull ncx, ull ncy, ull ncz) {
    ull dx = add2(X, ncx), dy = add2(Y, ncy), dz = add2(Z, ncz);
    return add2(add2(mul2(dx, dx), mul2(dy, dy)), mul2(dz, dz));
}
__device__ __forceinline__ ull umax64(ull a, ull b) { return a > b ? a : b; }

__device__ __forceinline__ float sqdist(float ax, float ay, float az,
                                        float bx, float by, float bz) {
    float dx = ax - bx, dy = ay - by, dz = az - bz;
    return __fadd_rn(__fadd_rn(__fmul_rn(dx, dx), __fmul_rn(dy, dy)), __fmul_rn(dz, dz));
}

// ---------------- Kernel A: farthest point sampling (v4: REDUX reduce) ----------------
// one block per batch, 256 threads, 16 points/thread in registers.
// Warp reduce: REDUX.MAX.U32 on dmin bits (non-negative floats are monotonic
// as unsigned) + ballot/ffs/shfl for the lowest tied index — exact same
// selection as the u64 shfl chain, ~110 cycles shorter critical path.
__global__ void __launch_bounds__(256) fps_kernel(const float* __restrict__ pos) {
    extern __shared__ float sm[];
    float* sx = sm;
    float* sy = sm + NN;
    float* sz = sm + 2 * NN;
    __shared__ alignas(16) ull skey[2][8];

    const int b = blockIdx.x;
    const int tid = threadIdx.x;
    const int lane = tid & 31;
    const float* pb = pos + (size_t)b * NN * 3;

    for (int i = tid; i < NN; i += 256) {
        sx[i] = pb[i * 3 + 0];
        sy[i] = pb[i * 3 + 1];
        sz[i] = pb[i * 3 + 2];
    }
    if (tid == 0) g_fps[b * MM] = 0;
    __syncthreads();

    const int base = tid * 16;
    ull X[8], Y[8], Z[8];
#pragma unroll
    for (int j = 0; j < 8; ++j) {
        X[j] = pack2(sx[base + 2 * j], sx[base + 2 * j + 1]);
        Y[j] = pack2(sy[base + 2 * j], sy[base + 2 * j + 1]);
        Z[j] = pack2(sz[base + 2 * j], sz[base + 2 * j + 1]);
    }
    float dmin[16];
#pragma unroll
    for (int j = 0; j < 16; ++j) dmin[j] = 1e10f;

    int last = 0;
    for (int it = 1; it < MM; ++it) {
        const float lx = sx[last], ly = sy[last], lz = sz[last];
        const ull nlx = bc2(-lx), nly = bc2(-ly), nlz = bc2(-lz);
        float bv = -1.0f; int bi = 0;
#pragma unroll
        for (int j = 0; j < 8; ++j) {
            ull s = sqdist2(X[j], Y[j], Z[j], nlx, nly, nlz);
            float d0, d1; unpack2(s, d0, d1);
            float m0 = fminf(dmin[2 * j + 0], d0); dmin[2 * j + 0] = m0;
            float m1 = fminf(dmin[2 * j + 1], d1); dmin[2 * j + 1] = m1;
            if (m0 > bv) { bv = m0; bi = base + 2 * j; }     // strict > keeps lowest idx
            if (m1 > bv) { bv = m1; bi = base + 2 * j + 1; }
        }
        // warp argmax via REDUX: dmin >= 0 so fp32 bits are order-isomorphic u32
        const unsigned bvb = __float_as_uint(bv);
        const unsigned mx  = __reduce_max_sync(0xffffffffu, bvb);
        const unsigned tie = __ballot_sync(0xffffffffu, bvb == mx);
        const int src = __ffs(tie) - 1;              // lowest lane = lowest index
        const int wbi = __shfl_sync(0xffffffffu, bi, src);

        const int p = it & 1;
        if (lane == 0)
            skey[p][tid >> 5] = (((ull)mx) << 32) | (unsigned)(4095 - wbi);
        __syncthreads();
        const ulonglong2* sk = reinterpret_cast<const ulonglong2*>(skey[p]);
        ulonglong2 a = sk[0], c = sk[1], d = sk[2], e = sk[3];
        ull m = umax64(umax64(umax64(a.x, a.y), umax64(c.x, c.y)),
                       umax64(umax64(d.x, d.y), umax64(e.x, e.y)));
        last = 4095 - (int)(m & 0xFFFFull);
        if (tid == 0) g_fps[b * MM + it] = last;
        // single barrier per iter: next iter writes skey[p^1]; skey[p] can only
        // be rewritten after the it+1 barrier, past which all reads completed.
    }
}

// ---------------- Kernel B: ball query + exact 64-NN selection (unchanged) ----------------
#define BCAP 512
__global__ void ballq_kernel(const float* __restrict__ pos) {
    extern __shared__ float sm[];
    float2* spx = (float2*)sm;
    float2* spy = spx + 2048;
    float2* spz = spy + 2048;
    ull* bufAll = (ull*)(spz + 2048);

    const int b = blockIdx.y;
    const int chunk = blockIdx.x;
    const int tid = threadIdx.x;
    const int warpId = tid >> 5;
    const int lane = tid & 31;
    const unsigned lanelt = (1u << lane) - 1u;
    const float* pb = pos + (size_t)b * NN * 3;

    for (int k = tid; k < NN * 3; k += 256) {
        float f = pb[k];
        int i = k / 3, comp = k - 3 * i;
        float* dst = (comp == 0) ? (float*)spx : (comp == 1) ? (float*)spy : (float*)spz;
        dst[(i & 2047) * 2 + (i >> 11)] = f;
    }
    __syncthreads();

    const ull* px = (const ull*)spx;
    const ull* py = (const ull*)spy;
    const ull* pz = (const ull*)spz;
    ull* buf = bufAll + (size_t)warpId * BCAP;

    for (int cc = 0; cc < 2; ++cc) {
        const int c = chunk * 16 + warpId * 2 + cc;
        const int gi = g_fps[b * MM + c];
        const int hi = gi >> 11, ii = gi & 2047;
        float2 t;
        t = spx[ii]; const float cx = hi ? t.y : t.x;
        t = spy[ii]; const float cy = hi ? t.y : t.x;
        t = spz[ii]; const float cz = hi ? t.y : t.x;
        const ull ncx = bc2(-cx), ncy = bc2(-cy), ncz = bc2(-cz);

        int cnt = 0;
        for (int basej = 0; basej < 2048; basej += 32) {
            const int j = basej + lane;
            ull s = sqdist2(px[j], py[j], pz[j], ncx, ncy, ncz);
            float d0, d1; unpack2(s, d0, d1);
            bool in0 = (d0 <= R2F);
            unsigned m0 = __ballot_sync(0xffffffffu, in0);
            if (in0) {
                int off = cnt + __popc(m0 & lanelt);
                if (off < BCAP)
                    buf[off] = (((ull)__float_as_uint(d0)) << 32) | (unsigned)j;
            }
            cnt += __popc(m0);
            bool in1 = (d1 <= R2F);
            unsigned m1 = __ballot_sync(0xffffffffu, in1);
            if (in1) {
                int off = cnt + __popc(m1 & lanelt);
                if (off < BCAP)
                    buf[off] = (((ull)__float_as_uint(d1)) << 32) | (unsigned)(j + 2048);
            }
            cnt += __popc(m1);
        }
        int ccnt = min(cnt, BCAP);
        __syncwarp();
        if (ccnt > KNB) {
            int n = KNB;
            while (n < ccnt) n <<= 1;
            for (int i = ccnt + lane; i < n; i += 32) buf[i] = 0xffffffffffffffffull;
            __syncwarp();
            for (int k2 = 2; k2 <= n; k2 <<= 1) {
                for (int j2 = k2 >> 1; j2 > 0; j2 >>= 1) {
                    for (int i = lane; i < n; i += 32) {
                        int ixj = i ^ j2;
                        if (ixj > i) {
                            ull a = buf[i], q = buf[ixj];
                            bool up = ((i & k2) == 0);
                            if ((a > q) == up) { buf[i] = q; buf[ixj] = a; }
                        }
                    }
                    __syncwarp();
                }
            }
        }
        int nv = min(ccnt, KNB);
        for (int s2 = lane; s2 < KNB; s2 += 32) {
            int outi = (s2 < nv) ? (int)(buf[s2] & 0xffffffffull) : -1;
            g_nbr[((size_t)(b * MM + c)) * KNB + s2] = outi;
        }
        __syncwarp();
    }
}

// ---------------- Kernel C: t = x @ W1[0:32,:] (unchanged) ----------------
__global__ void feat_kernel(const float* __restrict__ x, const float* __restrict__ W1) {
    __shared__ float Ws[CIN * 64];
    const int tid = threadIdx.x;
    for (int i = tid; i < CIN * 64; i += 256) Ws[i] = W1[i];
    __syncthreads();

    int g = blockIdx.x * 256 + tid;
    int p = g >> 2;
    int q = g & 3;

    float xr[32];
    const float4* xp = reinterpret_cast<const float4*>(x + (size_t)p * CIN);
#pragma unroll
    for (int k = 0; k < 8; ++k) {
        float4 v = xp[k];
        xr[4 * k + 0] = v.x; xr[4 * k + 1] = v.y; xr[4 * k + 2] = v.z; xr[4 * k + 3] = v.w;
    }
    float acc[16];
#pragma unroll
    for (int o = 0; o < 16; ++o) acc[o] = 0.0f;
#pragma unroll
    for (int i = 0; i < 32; ++i) {
        float xv = xr[i];
        const float4* wrow = reinterpret_cast<const float4*>(Ws + i * 64 + q * 16);
#pragma unroll
        for (int o4 = 0; o4 < 4; ++o4) {
            float4 w = wrow[o4];
            acc[o4 * 4 + 0] += xv * w.x;
            acc[o4 * 4 + 1] += xv * w.y;
            acc[o4 * 4 + 2] += xv * w.z;
            acc[o4 * 4 + 3] += xv * w.w;
        }
    }
    float4* tp = reinterpret_cast<float4*>(g_t + (size_t)p * 64 + q * 16);
#pragma unroll
    for (int o4 = 0; o4 < 4; ++o4)
        tp[o4] = make_float4(acc[o4 * 4 + 0], acc[o4 * 4 + 1], acc[o4 * 4 + 2], acc[o4 * 4 + 3]);
}

// ---------------- Kernel D: fused MLP + masked max-aggregate (v2, reverted) ----------------
// 256 threads = 4 groups of 64; launch_bounds(256,2) => <=128 regs, 2 blocks/SM.
#define SM_W3   4096
#define SM_W1P  12288
#define SM_B1   12480
#define SM_B2   12544
#define SM_B3   12608
#define SM_RED  12736
#define SM_H2   13760
#define SM_TOT2 21952   /* floats */

__global__ void __launch_bounds__(256, 2) conv_kernel(
    const float* __restrict__ pos,
    const float* __restrict__ W1, const float* __restrict__ b1,
    const float* __restrict__ W2, const float* __restrict__ b2,
    const float* __restrict__ W3, const float* __restrict__ b3,
    float* __restrict__ out, int out_size)
{
    extern __shared__ float sm[];
    const int tid = threadIdx.x;

    for (int i = tid; i < 4096; i += 256) sm[i] = W2[i];
    for (int i = tid; i < 8192; i += 256) sm[SM_W3 + i] = W3[i];
    if (tid < 192) sm[SM_W1P + tid] = W1[CIN * 64 + tid];
    if (tid < 64)  sm[SM_B1 + tid] = b1[tid];
    if (tid < 64)  sm[SM_B2 + tid] = b2[tid];
    if (tid < 128) sm[SM_B3 + tid] = b3[tid];
    __syncthreads();

    const int group = tid >> 6;
    const int gtid = tid & 63;
    const int lane = tid & 31;
    const int wgrp = (tid >> 5) & 1;
    const int cid = blockIdx.x * 4 + group;
    const int b = cid >> 10;

    const int gi = g_fps[cid];
    const float* pb = pos + (size_t)b * NN * 3;
    const float cx = pb[gi * 3 + 0], cy = pb[gi * 3 + 1], cz = pb[gi * 3 + 2];

    const int nj = g_nbr[(size_t)cid * KNB + gtid];
    const bool valid = (nj >= 0);
    const int jj = valid ? nj : gi;
    const float rx = pb[jj * 3 + 0] - cx;
    const float ry = pb[jj * 3 + 1] - cy;
    const float rz = pb[jj * 3 + 2] - cz;

    // ---- layer 1: h = relu(t + b1 + rel @ W1p) ----
    float h[64];
    const float4* tp = reinterpret_cast<const float4*>(g_t + ((size_t)b * NN + jj) * 64);
#pragma unroll
    for (int o4 = 0; o4 < 16; ++o4) {
        float4 tv = tp[o4];
        float4 bb = reinterpret_cast<const float4*>(sm + SM_B1)[o4];
        float4 w0 = reinterpret_cast<const float4*>(sm + SM_W1P)[o4];
        float4 w1 = reinterpret_cast<const float4*>(sm + SM_W1P + 64)[o4];
        float4 w2r = reinterpret_cast<const float4*>(sm + SM_W1P + 128)[o4];
        h[4 * o4 + 0] = fmaxf(tv.x + bb.x + rx * w0.x + ry * w1.x + rz * w2r.x, 0.0f);
        h[4 * o4 + 1] = fmaxf(tv.y + bb.y + rx * w0.y + ry * w1.y + rz * w2r.y, 0.0f);
        h[4 * o4 + 2] = fmaxf(tv.z + bb.z + rx * w0.z + ry * w1.z + rz * w2r.z, 0.0f);
        h[4 * o4 + 3] = fmaxf(tv.w + bb.w + rx * w0.w + ry * w1.w + rz * w2r.w, 0.0f);
    }

    // ---- layer 2 half 0: outputs [0,32) -> smem H2[c*256+tid] ----
    {
        ull acc[16];
#pragma unroll
        for (int q = 0; q < 16; ++q)
            acc[q] = pack2(sm[SM_B2 + 2 * q], sm[SM_B2 + 2 * q + 1]);
#pragma unroll
        for (int i = 0; i < 64; ++i) {
            ull hv = bc2(h[i]);
            const ulonglong2* wr = reinterpret_cast<const ulonglong2*>(sm + i * 64);
#pragma unroll
            for (int q = 0; q < 8; ++q) {
                ulonglong2 w = wr[q];
                fma2(acc[2 * q + 0], hv, w.x);
                fma2(acc[2 * q + 1], hv, w.y);
            }
        }
#pragma unroll
        for (int q = 0; q < 16; ++q) {
            float lo, hi;
            unpack2(acc[q], lo, hi);
            sm[SM_H2 + (2 * q + 0) * 256 + tid] = fmaxf(lo, 0.0f);
            sm[SM_H2 + (2 * q + 1) * 256 + tid] = fmaxf(hi, 0.0f);
        }
    }
    // ---- layer 2 half 1: outputs [32,64) -> h[32..63], then reload h[0..31] ----
    {
        ull acc[16];
#pragma unroll
        for (int q = 0; q < 16; ++q)
            acc[q] = pack2(sm[SM_B2 + 32 + 2 * q], sm[SM_B2 + 32 + 2 * q + 1]);
#pragma unroll
        for (int i = 0; i < 64; ++i) {
            ull hv = bc2(h[i]);
            const ulonglong2* wr = reinterpret_cast<const ulonglong2*>(sm + i * 64 + 32);
#pragma unroll
            for (int q = 0; q < 8; ++q) {
                ulonglong2 w = wr[q];
                fma2(acc[2 * q + 0], hv, w.x);
                fma2(acc[2 * q + 1], hv, w.y);
            }
        }
#pragma unroll
        for (int q = 0; q < 16; ++q) {
            float lo, hi;
            unpack2(acc[q], lo, hi);
            h[32 + 2 * q + 0] = fmaxf(lo, 0.0f);
            h[32 + 2 * q + 1] = fmaxf(hi, 0.0f);
        }
#pragma unroll
        for (int c = 0; c < 32; ++c)
            h[c] = sm[SM_H2 + c * 256 + tid];
    }

    // ---- layer 3 (4 tiles of 32 out) + masked max reduce ----
    for (int tile = 0; tile < 4; ++tile) {
        ull a3[16];
#pragma unroll
        for (int q = 0; q < 16; ++q)
            a3[q] = pack2(sm[SM_B3 + tile * 32 + 2 * q], sm[SM_B3 + tile * 32 + 2 * q + 1]);
#pragma unroll
        for (int i = 0; i < 64; ++i) {
            ull hv = bc2(h[i]);
            const ulonglong2* wr = reinterpret_cast<const ulonglong2*>(sm + SM_W3 + i * 128 + tile * 32);
#pragma unroll
            for (int q = 0; q < 8; ++q) {
                ulonglong2 w = wr[q];
                fma2(a3[2 * q + 0], hv, w.x);
                fma2(a3[2 * q + 1], hv, w.y);
            }
        }
        float v[32];
#pragma unroll
        for (int q = 0; q < 16; ++q) {
            float lo, hi;
            unpack2(a3[q], lo, hi);
            v[2 * q + 0] = valid ? lo : NEGV;
            v[2 * q + 1] = valid ? hi : NEGV;
        }
#pragma unroll
        for (int s = 16; s; s >>= 1) {
#pragma unroll
            for (int c = 0; c < 32; ++c)
                v[c] = fmaxf(v[c], __shfl_xor_sync(0xffffffffu, v[c], s));
        }
        float* red = sm + SM_RED + ((group * 4 + tile) * 2 + wgrp) * 32;
        if (lane == 0) {
#pragma unroll
            for (int q = 0; q < 8; ++q)
                reinterpret_cast<float4*>(red)[q] =
                    make_float4(v[4 * q + 0], v[4 * q + 1], v[4 * q + 2], v[4 * q + 3]);
        }
        __syncthreads();
        if (wgrp == 0) {
            const float* redA = sm + SM_RED + ((group * 4 + tile) * 2) * 32;
            float a = redA[lane];
            float bq = redA[32 + lane];
            int off = cid * 128 + tile * 32 + lane;
            if (off < out_size) out[off] = fmaxf(a, bq);
        }
    }
}

// ---------------- Kernel E: pos_out + batch_out tails ----------------
__global__ void tail_kernel(const float* __restrict__ pos, float* __restrict__ out, int out_size) {
    int i = blockIdx.x * 256 + threadIdx.x;
    if (i >= BB * MM) return;
    int b = i >> 10;
    int gi = g_fps[i];
    const float* pb = pos + (size_t)b * NN * 3;
    const int OX = BB * MM * 128;
    const int OP = OX + BB * MM * 3;
    const int OT = OP + BB * MM;
    if (out_size >= OP) {
        out[OX + i * 3 + 0] = pb[gi * 3 + 0];
        out[OX + i * 3 + 1] = pb[gi * 3 + 1];
        out[OX + i * 3 + 2] = pb[gi * 3 + 2];
    }
    if (out_size >= OT) out[OP + i] = (float)b;
}

extern "C" void kernel_launch(void* const* d_in, const int* in_sizes, int n_in,
                              void* d_out, int out_size) {
    const float* x   = (const float*)d_in[0];
    const float* pos = (const float*)d_in[1];
    const float* W1  = (const float*)d_in[3];
    const float* b1  = (const float*)d_in[4];
    const float* W2  = (const float*)d_in[5];
    const float* b2  = (const float*)d_in[6];
    const float* W3  = (const float*)d_in[7];
    const float* b3  = (const float*)d_in[8];
    float* out = (float*)d_out;

    const int smA = 3 * NN * 4;                        // 49152
    const int smB = 3 * NN * 4 + 8 * BCAP * 8;         // 81920
    const int smD = SM_TOT2 * 4;                       // 87808

    cudaFuncSetAttribute(fps_kernel,   cudaFuncAttributeMaxDynamicSharedMemorySize, smA);
    cudaFuncSetAttribute(ballq_kernel, cudaFuncAttributeMaxDynamicSharedMemorySize, smB);
    cudaFuncSetAttribute(conv_kernel,  cudaFuncAttributeMaxDynamicSharedMemorySize, smD);
    cudaFuncSetAttribute(fps_kernel,   cudaFuncAttributePreferredSharedMemoryCarveout, 100);
    cudaFuncSetAttribute(ballq_kernel, cudaFuncAttributePreferredSharedMemoryCarveout, 100);
    cudaFuncSetAttribute(conv_kernel,  cudaFuncAttributePreferredSharedMemoryCarveout, 100);

    fps_kernel<<<BB, 256, smA>>>(pos);
    ballq_kernel<<<dim3(64, BB), 256, smB>>>(pos);
    feat_kernel<<<(BB * NN * 4) / 256, 256>>>(x, W1);
    conv_kernel<<<(BB * MM) / 4, 256, smD>>>(pos, W1, b1, W2, b2, W3, b3, out, out_size);
    tail_kernel<<<(BB * MM) / 256, 256>>>(pos, out, out_size);
}

// round 15
// speedup vs baseline: 1.6557x; 1.0988x over previous
#include <cuda_runtime.h>
#include <cuda_bf16.h>
#include <cstdint>

// Problem constants
#define BB   8
#define NN   4096
#define MM   1024
#define CIN  32
#define KNB  64
#define NEGV (-1e10f)
#define R2F  (0.04f)

// Scratch (device globals: allocation-free)
__device__ int   g_fps[BB * MM];
__device__ float g_t[(size_t)BB * NN * 64];
__device__ int   g_nbr[(size_t)BB * MM * KNB];

typedef unsigned long long ull;

// ---------------- helpers: packed f32x2 ----------------
__device__ __forceinline__ ull pack2(float lo, float hi) {
    ull r; asm("mov.b64 %0, {%1, %2};" : "=l"(r) : "f"(lo), "f"(hi)); return r;
}
__device__ __forceinline__ ull bc2(float v) {
    ull r; asm("mov.b64 %0, {%1, %1};" : "=l"(r) : "f"(v)); return r;
}
__device__ __forceinline__ void unpack2(ull v, float& lo, float& hi) {
    asm("mov.b64 {%0, %1}, %2;" : "=f"(lo), "=f"(hi) : "l"(v));
}
__device__ __forceinline__ void fma2(ull& acc, ull a, ull b) {
    asm("fma.rn.f32x2 %0, %1, %2, %0;" : "+l"(acc) : "l"(a), "l"(b));
}
__device__ __forceinline__ ull add2(ull a, ull b) {
    ull r; asm("add.rn.f32x2 %0, %1, %2;" : "=l"(r) : "l"(a), "l"(b)); return r;
}
__device__ __forceinline__ ull mul2(ull a, ull b) {
    ull r; asm("mul.rn.f32x2 %0, %1, %2;" : "=l"(r) : "l"(a), "l"(b)); return r;
}
// per-component identical to __fadd_rn(__fadd_rn(__fmul_rn,__fmul_rn),__fmul_rn)
__device__ __forceinline__ ull sqdist2(ull X, ull Y, ull Z, ull ncx, ull ncy, ull ncz) {
    ull dx = add2(X, ncx), dy = add2(Y, ncy), dz = add2(Z, ncz);
    return add2(add2(mul2(dx, dx), mul2(dy, dy)), mul2(dz, dz));
}
__device__ __forceinline__ ull umax64(ull a, ull b) { return a > b ? a : b; }

__device__ __forceinline__ float sqdist(float ax, float ay, float az,
                                        float bx, float by, float bz) {
    float dx = ax - bx, dy = ay - by, dz = az - bz;
    return __fadd_rn(__fadd_rn(__fmul_rn(dx, dx), __fmul_rn(dy, dy)), __fmul_rn(dz, dz));
}

// ---------------- Kernel A: farthest point sampling (v4, unchanged) ----------------
__global__ void __launch_bounds__(256) fps_kernel(const float* __restrict__ pos) {
    extern __shared__ float sm[];
    float* sx = sm;
    float* sy = sm + NN;
    float* sz = sm + 2 * NN;
    __shared__ alignas(16) ull skey[2][8];

    const int b = blockIdx.x;
    const int tid = threadIdx.x;
    const int lane = tid & 31;
    const float* pb = pos + (size_t)b * NN * 3;

    for (int i = tid; i < NN; i += 256) {
        sx[i] = pb[i * 3 + 0];
        sy[i] = pb[i * 3 + 1];
        sz[i] = pb[i * 3 + 2];
    }
    if (tid == 0) g_fps[b * MM] = 0;
    __syncthreads();

    const int base = tid * 16;
    ull X[8], Y[8], Z[8];
#pragma unroll
    for (int j = 0; j < 8; ++j) {
        X[j] = pack2(sx[base + 2 * j], sx[base + 2 * j + 1]);
        Y[j] = pack2(sy[base + 2 * j], sy[base + 2 * j + 1]);
        Z[j] = pack2(sz[base + 2 * j], sz[base + 2 * j + 1]);
    }
    float dmin[16];
#pragma unroll
    for (int j = 0; j < 16; ++j) dmin[j] = 1e10f;

    int last = 0;
    for (int it = 1; it < MM; ++it) {
        const float lx = sx[last], ly = sy[last], lz = sz[last];
        const ull nlx = bc2(-lx), nly = bc2(-ly), nlz = bc2(-lz);
        float bv = -1.0f; int bi = 0;
#pragma unroll
        for (int j = 0; j < 8; ++j) {
            ull s = sqdist2(X[j], Y[j], Z[j], nlx, nly, nlz);
            float d0, d1; unpack2(s, d0, d1);
            float m0 = fminf(dmin[2 * j + 0], d0); dmin[2 * j + 0] = m0;
            float m1 = fminf(dmin[2 * j + 1], d1); dmin[2 * j + 1] = m1;
            if (m0 > bv) { bv = m0; bi = base + 2 * j; }
            if (m1 > bv) { bv = m1; bi = base + 2 * j + 1; }
        }
        const unsigned bvb = __float_as_uint(bv);
        const unsigned mx  = __reduce_max_sync(0xffffffffu, bvb);
        const unsigned tie = __ballot_sync(0xffffffffu, bvb == mx);
        const int src = __ffs(tie) - 1;
        const int wbi = __shfl_sync(0xffffffffu, bi, src);

        const int p = it & 1;
        if (lane == 0)
            skey[p][tid >> 5] = (((ull)mx) << 32) | (unsigned)(4095 - wbi);
        __syncthreads();
        const ulonglong2* sk = reinterpret_cast<const ulonglong2*>(skey[p]);
        ulonglong2 a = sk[0], c = sk[1], d = sk[2], e = sk[3];
        ull m = umax64(umax64(umax64(a.x, a.y), umax64(c.x, c.y)),
                       umax64(umax64(d.x, d.y), umax64(e.x, e.y)));
        last = 4095 - (int)(m & 0xFFFFull);
        if (tid == 0) g_fps[b * MM + it] = last;
    }
}

// ---------------- Kernel B: ball query + exact 64-NN selection (unchanged) ----------------
#define BCAP 512
__global__ void ballq_kernel(const float* __restrict__ pos) {
    extern __shared__ float sm[];
    float2* spx = (float2*)sm;
    float2* spy = spx + 2048;
    float2* spz = spy + 2048;
    ull* bufAll = (ull*)(spz + 2048);

    const int b = blockIdx.y;
    const int chunk = blockIdx.x;
    const int tid = threadIdx.x;
    const int warpId = tid >> 5;
    const int lane = tid & 31;
    const unsigned lanelt = (1u << lane) - 1u;
    const float* pb = pos + (size_t)b * NN * 3;

    for (int k = tid; k < NN * 3; k += 256) {
        float f = pb[k];
        int i = k / 3, comp = k - 3 * i;
        float* dst = (comp == 0) ? (float*)spx : (comp == 1) ? (float*)spy : (float*)spz;
        dst[(i & 2047) * 2 + (i >> 11)] = f;
    }
    __syncthreads();

    const ull* px = (const ull*)spx;
    const ull* py = (const ull*)spy;
    const ull* pz = (const ull*)spz;
    ull* buf = bufAll + (size_t)warpId * BCAP;

    for (int cc = 0; cc < 2; ++cc) {
        const int c = chunk * 16 + warpId * 2 + cc;
        const int gi = g_fps[b * MM + c];
        const int hi = gi >> 11, ii = gi & 2047;
        float2 t;
        t = spx[ii]; const float cx = hi ? t.y : t.x;
        t = spy[ii]; const float cy = hi ? t.y : t.x;
        t = spz[ii]; const float cz = hi ? t.y : t.x;
        const ull ncx = bc2(-cx), ncy = bc2(-cy), ncz = bc2(-cz);

        int cnt = 0;
        for (int basej = 0; basej < 2048; basej += 32) {
            const int j = basej + lane;
            ull s = sqdist2(px[j], py[j], pz[j], ncx, ncy, ncz);
            float d0, d1; unpack2(s, d0, d1);
            bool in0 = (d0 <= R2F);
            unsigned m0 = __ballot_sync(0xffffffffu, in0);
            if (in0) {
                int off = cnt + __popc(m0 & lanelt);
                if (off < BCAP)
                    buf[off] = (((ull)__float_as_uint(d0)) << 32) | (unsigned)j;
            }
            cnt += __popc(m0);
            bool in1 = (d1 <= R2F);
            unsigned m1 = __ballot_sync(0xffffffffu, in1);
            if (in1) {
                int off = cnt + __popc(m1 & lanelt);
                if (off < BCAP)
                    buf[off] = (((ull)__float_as_uint(d1)) << 32) | (unsigned)(j + 2048);
            }
            cnt += __popc(m1);
        }
        int ccnt = min(cnt, BCAP);
        __syncwarp();
        if (ccnt > KNB) {
            int n = KNB;
            while (n < ccnt) n <<= 1;
            for (int i = ccnt + lane; i < n; i += 32) buf[i] = 0xffffffffffffffffull;
            __syncwarp();
            for (int k2 = 2; k2 <= n; k2 <<= 1) {
                for (int j2 = k2 >> 1; j2 > 0; j2 >>= 1) {
                    for (int i = lane; i < n; i += 32) {
                        int ixj = i ^ j2;
                        if (ixj > i) {
                            ull a = buf[i], q = buf[ixj];
                            bool up = ((i & k2) == 0);
                            if ((a > q) == up) { buf[i] = q; buf[ixj] = a; }
                        }
                    }
                    __syncwarp();
                }
            }
        }
        int nv = min(ccnt, KNB);
        for (int s2 = lane; s2 < KNB; s2 += 32) {
            int outi = (s2 < nv) ? (int)(buf[s2] & 0xffffffffull) : -1;
            g_nbr[((size_t)(b * MM + c)) * KNB + s2] = outi;
        }
        __syncwarp();
    }
}

// ---------------- Kernel C: t = x @ W1[0:32,:] (unchanged) ----------------
__global__ void feat_kernel(const float* __restrict__ x, const float* __restrict__ W1) {
    __shared__ float Ws[CIN * 64];
    const int tid = threadIdx.x;
    for (int i = tid; i < CIN * 64; i += 256) Ws[i] = W1[i];
    __syncthreads();

    int g = blockIdx.x * 256 + tid;
    int p = g >> 2;
    int q = g & 3;

    float xr[32];
    const float4* xp = reinterpret_cast<const float4*>(x + (size_t)p * CIN);
#pragma unroll
    for (int k = 0; k < 8; ++k) {
        float4 v = xp[k];
        xr[4 * k + 0] = v.x; xr[4 * k + 1] = v.y; xr[4 * k + 2] = v.z; xr[4 * k + 3] = v.w;
    }
    float acc[16];
#pragma unroll
    for (int o = 0; o < 16; ++o) acc[o] = 0.0f;
#pragma unroll
    for (int i = 0; i < 32; ++i) {
        float xv = xr[i];
        const float4* wrow = reinterpret_cast<const float4*>(Ws + i * 64 + q * 16);
#pragma unroll
        for (int o4 = 0; o4 < 4; ++o4) {
            float4 w = wrow[o4];
            acc[o4 * 4 + 0] += xv * w.x;
            acc[o4 * 4 + 1] += xv * w.y;
            acc[o4 * 4 + 2] += xv * w.z;
            acc[o4 * 4 + 3] += xv * w.w;
        }
    }
    float4* tp = reinterpret_cast<float4*>(g_t + (size_t)p * 64 + q * 16);
#pragma unroll
    for (int o4 = 0; o4 < 4; ++o4)
        tp[o4] = make_float4(acc[o4 * 4 + 0], acc[o4 * 4 + 1], acc[o4 * 4 + 2], acc[o4 * 4 + 3]);
}

// ---------------- Kernel D v5: warp-per-centroid, 2 neighbors/thread ----------------
// 128 threads = 4 warps = 4 centroids. Each thread owns neighbors (lane, lane+32):
// one weight ull load feeds TWO fma2 (4 B smem traffic per fma2, no dup-MOVs).
// H2 parking region is thread-private smem (same thread writes & reads: no barrier).
#define C5_W2   0        /* 4096 floats */
#define C5_W3   4096     /* 8192 */
#define C5_W1P  12288    /* 192  */
#define C5_B1   12480    /* 64   */
#define C5_B2   12544    /* 64   */
#define C5_B3   12608    /* 128  */
#define C5_H2   12736    /* 8192 floats = 4096 ull: [q 0..15][slot 0..1][tid 0..127] */
#define C5_TOT  20928

__global__ void __launch_bounds__(128, 2) conv_kernel(
    const float* __restrict__ pos,
    const float* __restrict__ W1, const float* __restrict__ b1,
    const float* __restrict__ W2, const float* __restrict__ b2,
    const float* __restrict__ W3, const float* __restrict__ b3,
    float* __restrict__ out, int out_size)
{
    extern __shared__ float smf[];
    const int tid = threadIdx.x;

    for (int i = tid; i < 4096; i += 128) smf[C5_W2 + i] = W2[i];
    for (int i = tid; i < 8192; i += 128) smf[C5_W3 + i] = W3[i];
    for (int i = tid; i < 192; i += 128)  smf[C5_W1P + i] = W1[CIN * 64 + i];
    if (tid < 64) smf[C5_B1 + tid] = b1[tid];
    if (tid < 64) smf[C5_B2 + tid] = b2[tid];
    smf[C5_B3 + tid] = b3[tid];
    __syncthreads();

    const int warp = tid >> 5;
    const int lane = tid & 31;
    const int cid = blockIdx.x * 4 + warp;
    const int b = cid >> 10;

    const int gi = g_fps[cid];
    const float* pb = pos + (size_t)b * NN * 3;
    const float cx = pb[gi * 3 + 0], cy = pb[gi * 3 + 1], cz = pb[gi * 3 + 2];

    const int nj0 = g_nbr[(size_t)cid * KNB + lane];
    const int nj1 = g_nbr[(size_t)cid * KNB + lane + 32];
    const bool vld0 = (nj0 >= 0), vld1 = (nj1 >= 0);
    const int jj0 = vld0 ? nj0 : gi;
    const int jj1 = vld1 ? nj1 : gi;
    const float rx0 = pb[jj0 * 3 + 0] - cx, ry0 = pb[jj0 * 3 + 1] - cy, rz0 = pb[jj0 * 3 + 2] - cz;
    const float rx1 = pb[jj1 * 3 + 0] - cx, ry1 = pb[jj1 * 3 + 1] - cy, rz1 = pb[jj1 * 3 + 2] - cz;

    // ---- layer 1 for both neighbors (same expression as proven v2) ----
    float h0[64], h1[64];
    {
        const float4* tp0 = reinterpret_cast<const float4*>(g_t + ((size_t)b * NN + jj0) * 64);
        const float4* tp1 = reinterpret_cast<const float4*>(g_t + ((size_t)b * NN + jj1) * 64);
#pragma unroll
        for (int o4 = 0; o4 < 16; ++o4) {
            float4 bb  = reinterpret_cast<const float4*>(smf + C5_B1)[o4];
            float4 w0  = reinterpret_cast<const float4*>(smf + C5_W1P)[o4];
            float4 w1  = reinterpret_cast<const float4*>(smf + C5_W1P + 64)[o4];
            float4 w2v = reinterpret_cast<const float4*>(smf + C5_W1P + 128)[o4];
            float4 ta = tp0[o4];
            h0[4 * o4 + 0] = fmaxf(ta.x + bb.x + rx0 * w0.x + ry0 * w1.x + rz0 * w2v.x, 0.0f);
            h0[4 * o4 + 1] = fmaxf(ta.y + bb.y + rx0 * w0.y + ry0 * w1.y + rz0 * w2v.y, 0.0f);
            h0[4 * o4 + 2] = fmaxf(ta.z + bb.z + rx0 * w0.z + ry0 * w1.z + rz0 * w2v.z, 0.0f);
            h0[4 * o4 + 3] = fmaxf(ta.w + bb.w + rx0 * w0.w + ry0 * w1.w + rz0 * w2v.w, 0.0f);
            float4 tb = tp1[o4];
            h1[4 * o4 + 0] = fmaxf(tb.x + bb.x + rx1 * w0.x + ry1 * w1.x + rz1 * w2v.x, 0.0f);
            h1[4 * o4 + 1] = fmaxf(tb.y + bb.y + rx1 * w0.y + ry1 * w1.y + rz1 * w2v.y, 0.0f);
            h1[4 * o4 + 2] = fmaxf(tb.z + bb.z + rx1 * w0.z + ry1 * w1.z + rz1 * w2v.z, 0.0f);
            h1[4 * o4 + 3] = fmaxf(tb.w + bb.w + rx1 * w0.w + ry1 * w1.w + rz1 * w2v.w, 0.0f);
        }
    }

    ull* H2u = reinterpret_cast<ull*>(smf + C5_H2);
    const ull* b2u = reinterpret_cast<const ull*>(smf + C5_B2);

    // ---- layer 2: two 32-channel halves; one weight load feeds both neighbors ----
#pragma unroll 1
    for (int hf = 0; hf < 2; ++hf) {
        ull acc0[16], acc1[16];
#pragma unroll
        for (int q = 0; q < 16; ++q) { ull bv = b2u[hf * 16 + q]; acc0[q] = bv; acc1[q] = bv; }
#pragma unroll 8
        for (int k = 0; k < 64; ++k) {
            ull hv0 = bc2(h0[k]);
            ull hv1 = bc2(h1[k]);
            const ulonglong2* wr = reinterpret_cast<const ulonglong2*>(smf + C5_W2 + k * 64 + hf * 32);
#pragma unroll
            for (int q = 0; q < 8; ++q) {
                ulonglong2 w = wr[q];
                fma2(acc0[2 * q + 0], hv0, w.x);
                fma2(acc0[2 * q + 1], hv0, w.y);
                fma2(acc1[2 * q + 0], hv1, w.x);
                fma2(acc1[2 * q + 1], hv1, w.y);
            }
        }
        if (hf == 0) {
            // relu -> park in thread-private smem slots (no barrier needed)
#pragma unroll
            for (int q = 0; q < 16; ++q) {
                float lo, hi;
                unpack2(acc0[q], lo, hi);
                H2u[q * 256 + tid] = pack2(fmaxf(lo, 0.0f), fmaxf(hi, 0.0f));
                unpack2(acc1[q], lo, hi);
                H2u[q * 256 + 128 + tid] = pack2(fmaxf(lo, 0.0f), fmaxf(hi, 0.0f));
            }
        } else {
#pragma unroll
            for (int q = 0; q < 16; ++q) {
                float lo, hi;
                unpack2(acc0[q], lo, hi);
                h0[32 + 2 * q + 0] = fmaxf(lo, 0.0f);
                h0[32 + 2 * q + 1] = fmaxf(hi, 0.0f);
                unpack2(acc1[q], lo, hi);
                h1[32 + 2 * q + 0] = fmaxf(lo, 0.0f);
                h1[32 + 2 * q + 1] = fmaxf(hi, 0.0f);
            }
#pragma unroll
            for (int q = 0; q < 16; ++q) {
                float lo, hi;
                unpack2(H2u[q * 256 + tid], lo, hi);
                h0[2 * q + 0] = lo; h0[2 * q + 1] = hi;
                unpack2(H2u[q * 256 + 128 + tid], lo, hi);
                h1[2 * q + 0] = lo; h1[2 * q + 1] = hi;
            }
        }
    }

    // ---- layer 3: 4 passes of 32 channels + masked max (in-thread, then warp shfl) ----
    const ull* b3u = reinterpret_cast<const ull*>(smf + C5_B3);
#pragma unroll 1
    for (int p = 0; p < 4; ++p) {
        ull acc0[16], acc1[16];
#pragma unroll
        for (int q = 0; q < 16; ++q) { ull bv = b3u[p * 16 + q]; acc0[q] = bv; acc1[q] = bv; }
#pragma unroll 8
        for (int k = 0; k < 64; ++k) {
            ull hv0 = bc2(h0[k]);
            ull hv1 = bc2(h1[k]);
            const ulonglong2* wr = reinterpret_cast<const ulonglong2*>(smf + C5_W3 + k * 128 + p * 32);
#pragma unroll
            for (int q = 0; q < 8; ++q) {
                ulonglong2 w = wr[q];
                fma2(acc0[2 * q + 0], hv0, w.x);
                fma2(acc0[2 * q + 1], hv0, w.y);
                fma2(acc1[2 * q + 0], hv1, w.x);
                fma2(acc1[2 * q + 1], hv1, w.y);
            }
        }
        float v[32];
#pragma unroll
        for (int q = 0; q < 16; ++q) {
            float a, bq, c, d;
            unpack2(acc0[q], a, bq);
            unpack2(acc1[q], c, d);
            v[2 * q + 0] = fmaxf(vld0 ? a  : NEGV, vld1 ? c : NEGV);
            v[2 * q + 1] = fmaxf(vld0 ? bq : NEGV, vld1 ? d : NEGV);
        }
#pragma unroll
        for (int s = 16; s; s >>= 1) {
#pragma unroll
            for (int c2 = 0; c2 < 32; ++c2)
                v[c2] = fmaxf(v[c2], __shfl_xor_sync(0xffffffffu, v[c2], s));
        }
        if (lane == 0) {
            int base = cid * 128 + p * 32;
            if (base + 32 <= out_size) {
#pragma unroll
                for (int q4 = 0; q4 < 8; ++q4)
                    reinterpret_cast<float4*>(out + base)[q4] =
                        make_float4(v[4 * q4 + 0], v[4 * q4 + 1], v[4 * q4 + 2], v[4 * q4 + 3]);
            } else {
                for (int c2 = 0; c2 < 32; ++c2)
                    if (base + c2 < out_size) out[base + c2] = v[c2];
            }
        }
    }
}

// ---------------- Kernel E: pos_out + batch_out tails ----------------
__global__ void tail_kernel(const float* __restrict__ pos, float* __restrict__ out, int out_size) {
    int i = blockIdx.x * 256 + threadIdx.x;
    if (i >= BB * MM) return;
    int b = i >> 10;
    int gi = g_fps[i];
    const float* pb = pos + (size_t)b * NN * 3;
    const int OX = BB * MM * 128;
    const int OP = OX + BB * MM * 3;
    const int OT = OP + BB * MM;
    if (out_size >= OP) {
        out[OX + i * 3 + 0] = pb[gi * 3 + 0];
        out[OX + i * 3 + 1] = pb[gi * 3 + 1];
        out[OX + i * 3 + 2] = pb[gi * 3 + 2];
    }
    if (out_size >= OT) out[OP + i] = (float)b;
}

extern "C" void kernel_launch(void* const* d_in, const int* in_sizes, int n_in,
                              void* d_out, int out_size) {
    const float* x   = (const float*)d_in[0];
    const float* pos = (const float*)d_in[1];
    const float* W1  = (const float*)d_in[3];
    const float* b1  = (const float*)d_in[4];
    const float* W2  = (const float*)d_in[5];
    const float* b2  = (const float*)d_in[6];
    const float* W3  = (const float*)d_in[7];
    const float* b3  = (const float*)d_in[8];
    float* out = (float*)d_out;

    const int smA = 3 * NN * 4;                        // 49152
    const int smB = 3 * NN * 4 + 8 * BCAP * 8;         // 81920
    const int smD = C5_TOT * 4;                        // 83712

    cudaFuncSetAttribute(fps_kernel,   cudaFuncAttributeMaxDynamicSharedMemorySize, smA);
    cudaFuncSetAttribute(ballq_kernel, cudaFuncAttributeMaxDynamicSharedMemorySize, smB);
    cudaFuncSetAttribute(conv_kernel,  cudaFuncAttributeMaxDynamicSharedMemorySize, smD);
    cudaFuncSetAttribute(fps_kernel,   cudaFuncAttributePreferredSharedMemoryCarveout, 100);
    cudaFuncSetAttribute(ballq_kernel, cudaFuncAttributePreferredSharedMemoryCarveout, 100);
    cudaFuncSetAttribute(conv_kernel,  cudaFuncAttributePreferredSharedMemoryCarveout, 100);

    fps_kernel<<<BB, 256, smA>>>(pos);
    ballq_kernel<<<dim3(64, BB), 256, smB>>>(pos);
    feat_kernel<<<(BB * NN * 4) / 256, 256>>>(x, W1);
    conv_kernel<<<(BB * MM) / 4, 128, smD>>>(pos, W1, b1, W2, b2, W3, b3, out, out_size);
    tail_kernel<<<(BB * MM) / 256, 256>>>(pos, out, out_size);
}